// round 15
// baseline (speedup 1.0000x reference)
#include <cuda_runtime.h>
#include <cuda_bf16.h>
#include <mma.h>
#include <math.h>
#include <stdint.h>

using namespace nvcuda;

#define NUM_NEURONS 2048
#define D_MODEL     1024
#define BATCH       64
#define K_TOTAL     4096
#define KSPLIT      32
#define DCHUNK      128
#define XLD         132                       // padded x_sh row stride (floats)

// GEMM tiling (R13/R14-proven)
#define KK        32
#define NSTAGE    ((K_TOTAL / KSPLIT) / KK)   // 4
#define LDM       40
#define OFF_AL    (64 * LDM)
#define OFF_BH    (2 * 64 * LDM)
#define OFF_BL    (OFF_BH + 128 * LDM)
#define STAGE_EL  (OFF_BL + 128 * LDM)
#define SMEM_B    (2 * STAGE_EL * 2)          // 61440 bytes

// Scratch (static device globals — no runtime allocation)
__device__ __align__(256) __nv_bfloat16 g_Ahi[BATCH * K_TOTAL];    // S^T hi [b][k]
__device__ __align__(256) __nv_bfloat16 g_Alo[BATCH * K_TOTAL];    // S^T lo
__device__ __align__(256) float g_part[KSPLIT * BATCH * D_MODEL];  // 8MB

// ---------------------------------------------------------------------------
// FMA-pipe sincos (R3-proven).
// ---------------------------------------------------------------------------
__device__ __forceinline__ void sincos_poly(float th, float& s_out, float& c_out) {
    const float TWO_OVER_PI = 0.636619772f;
    const float MAGIC = 12582912.0f;
    float w   = th * TWO_OVER_PI;
    float big = w + MAGIC;
    int   qi  = __float_as_int(big);
    float r   = big - MAGIC;
    float u   = w - r;
    float u2  = u * u;
    float sp  = fmaf(u2, fmaf(u2, fmaf(u2, -4.6817541e-3f, 7.9692626e-2f),
                              -6.4596410e-1f), 1.57079633f) * u;
    float cp  = fmaf(u2, fmaf(u2, fmaf(u2, -2.0864648e-2f, 2.5369510e-1f),
                              -1.2337006f), 1.0f);
    float ss = (qi & 1) ? cp : sp;
    float cc = (qi & 1) ? sp : cp;
    if (qi & 2)       ss = -ss;
    if ((qi + 1) & 2) cc = -cc;
    s_out = ss; c_out = cc;
}

// ---------------------------------------------------------------------------
// Main: 2 neurons x 64 batches per CTA; 3/4 MUFU + 1/4 FMA-pipe poly;
// rotation identity for +t (R14-proven). NEW: x_sh in [b][d] layout with
// 132-float row stride -> inner-loop LDS.128 for x (conflict-free) and
// float4 rB reads: 3 LDS.128 per 4 elems instead of 8 LDS (issue-bound fix).
// x staged straight from input x[b][d] — prep_x/g_xT deleted.
// Writes bf16 hi/lo S^T directly.
// ---------------------------------------------------------------------------
__global__ __launch_bounds__(128) void resonant_main(const float* __restrict__ x,
                                                     const float* __restrict__ t,
                                                     const float* __restrict__ W,
                                                     const float* __restrict__ Bp) {
    __shared__ __align__(16) float  x_sh[BATCH * XLD];   // 33 KB
    __shared__ __align__(16) float2 rB_sh[2][DCHUNK];    // 2 KB

    int tid = threadIdx.x;
    int b   = tid & 63;
    int nl  = tid >> 6;
    int n0  = blockIdx.x * 2;

    float tb = t[b];
    float cp = 0.0f, sp = 0.0f;

    const float* xrow = &x_sh[b * XLD];

    // staging ownership: 2 threads per batch row, interleaved 16-float blocks
    int bq = tid >> 1;
    int h  = tid & 1;

    for (int d0 = 0; d0 < D_MODEL; d0 += DCHUNK) {
        // stage x[bq][d0 + h*16 + blk*32 + inner*4], conflict-free STS.128
        {
            const float4* src = reinterpret_cast<const float4*>(x + bq * D_MODEL + d0);
            #pragma unroll
            for (int q = 0; q < 16; q++) {
                int blk = q >> 2, inner = q & 3;
                int dof = h * 16 + blk * 32 + inner * 4;     // 0..124
                float4 v = src[dof >> 2];
                *reinterpret_cast<float4*>(&x_sh[bq * XLD + dof]) = v;
            }
        }
        {
            float w0 = W [(n0 + 0) * D_MODEL + d0 + tid];
            float p0 = Bp[(n0 + 0) * D_MODEL + d0 + tid];
            rB_sh[0][tid] = make_float2(__fdividef(1.0f, 1.0f + fabsf(w0)), p0);
            float w1 = W [(n0 + 1) * D_MODEL + d0 + tid];
            float p1 = Bp[(n0 + 1) * D_MODEL + d0 + tid];
            rB_sh[1][tid] = make_float2(__fdividef(1.0f, 1.0f + fabsf(w1)), p1);
        }
        __syncthreads();

        #pragma unroll
        for (int dd = 0; dd < DCHUNK; dd += 4) {
            float4 xv  = *reinterpret_cast<const float4*>(xrow + dd);
            float4 r01 = *reinterpret_cast<const float4*>(&rB_sh[nl][dd]);     // {r0,B0,r1,B1}
            float4 r23 = *reinterpret_cast<const float4*>(&rB_sh[nl][dd + 2]); // {r2,B2,r3,B3}
            float s, c;
            // 3 MUFU-path elements
            {
                float th = fmaf(xv.x, r01.x, r01.y);
                __sincosf(th, &s, &c); cp += c; sp += s;
            }
            {
                float th = fmaf(xv.y, r01.z, r01.w);
                __sincosf(th, &s, &c); cp += c; sp += s;
            }
            {
                float th = fmaf(xv.z, r23.x, r23.y);
                __sincosf(th, &s, &c); cp += c; sp += s;
            }
            // 1 FMA-pipe poly element
            {
                float th = fmaf(xv.w, r23.z, r23.w);
                sincos_poly(th, s, c); cp += c; sp += s;
            }
        }
        __syncthreads();
    }

    // rotate by t_b (exact identity)
    float st_, ct_;
    __sincosf(tb, &st_, &ct_);
    float cs = ct_ * cp - st_ * sp;
    float sn = st_ * cp + ct_ * sp;

    int n = n0 + nl;
    __nv_bfloat16 ch = __float2bfloat16(cs);
    g_Ahi[b * K_TOTAL + n] = ch;
    g_Alo[b * K_TOTAL + n] = __float2bfloat16(cs - __bfloat162float(ch));
    __nv_bfloat16 sh = __float2bfloat16(sn);
    g_Ahi[b * K_TOTAL + n + NUM_NEURONS] = sh;
    g_Alo[b * K_TOTAL + n + NUM_NEURONS] = __float2bfloat16(sn - __bfloat162float(sh));
}

// ---------------------------------------------------------------------------
// bf16 hi/lo split of a float4 into two packed uint2.
// ---------------------------------------------------------------------------
__device__ __forceinline__ void split4(float4 v, uint2& hi, uint2& lo) {
    __nv_bfloat162 h0 = __floats2bfloat162_rn(v.x, v.y);
    __nv_bfloat162 h1 = __floats2bfloat162_rn(v.z, v.w);
    float2 f0 = __bfloat1622float2(h0);
    float2 f1 = __bfloat1622float2(h1);
    __nv_bfloat162 l0 = __floats2bfloat162_rn(v.x - f0.x, v.y - f0.y);
    __nv_bfloat162 l1 = __floats2bfloat162_rn(v.z - f1.x, v.w - f1.y);
    hi.x = *reinterpret_cast<uint32_t*>(&h0);
    hi.y = *reinterpret_cast<uint32_t*>(&h1);
    lo.x = *reinterpret_cast<uint32_t*>(&l0);
    lo.y = *reinterpret_cast<uint32_t*>(&l1);
}

// ---------------------------------------------------------------------------
// Tensor-core GEMM (R14-proven): smem-staged wmma, double buffer, reg
// prefetch, inline fp32->bf16 hi/lo conversion of P during staging.
// CTA = 64b x 128j, 8 warps, 4 stages of KK=32; grid (8,32)=256 CTAs.
// hi*hi + lo*hi + hi*lo, fp32 acc; disjoint partials.
// ---------------------------------------------------------------------------
__global__ __launch_bounds__(256) void gemm_wmma(const float* __restrict__ Pr,
                                                 const float* __restrict__ Pi) {
    extern __shared__ __nv_bfloat16 sm[];

    int tid  = threadIdx.x;
    int warp = tid >> 5;
    int wb   = (warp >> 2) * 32;
    int wj   = (warp & 3) * 32;
    int j0   = blockIdx.x * 128;
    int k0   = blockIdx.y * (K_TOTAL / KSPLIT);

    const float* P     = (k0 < NUM_NEURONS) ? Pr : Pi;
    int          kbase = (k0 < NUM_NEURONS) ? k0 : k0 - NUM_NEURONS;

    int arow = tid >> 2, achk = (tid & 3) * 8;
    const __nv_bfloat16* gAh = g_Ahi + arow * K_TOTAL + k0 + achk;
    const __nv_bfloat16* gAl = g_Alo + arow * K_TOTAL + k0 + achk;
    int brow0 = tid >> 1, bchk0 = (tid & 1) * 16;
    const float* gB = P + (j0 + brow0) * NUM_NEURONS + kbase + bchk0;

    uint32_t aDst = arow * LDM + achk;
    uint32_t bDst = brow0 * LDM + bchk0;

    wmma::fragment<wmma::matrix_a, 16, 16, 16, __nv_bfloat16, wmma::row_major> aH[2], aL[2];
    wmma::fragment<wmma::matrix_b, 16, 16, 16, __nv_bfloat16, wmma::col_major> bH[2], bL[2];
    wmma::fragment<wmma::accumulator, 16, 16, 16, float> c[2][2];
    #pragma unroll
    for (int i = 0; i < 2; i++)
        #pragma unroll
        for (int j = 0; j < 2; j++) wmma::fill_fragment(c[i][j], 0.0f);

    {   // stage 0
        __nv_bfloat16* st = sm;
        *reinterpret_cast<uint4*>(st + aDst)          = *reinterpret_cast<const uint4*>(gAh);
        *reinterpret_cast<uint4*>(st + OFF_AL + aDst) = *reinterpret_cast<const uint4*>(gAl);
        #pragma unroll
        for (int q = 0; q < 4; q++) {
            float4 v = reinterpret_cast<const float4*>(gB)[q];
            uint2 h, l;
            split4(v, h, l);
            *reinterpret_cast<uint2*>(st + OFF_BH + bDst + q * 4) = h;
            *reinterpret_cast<uint2*>(st + OFF_BL + bDst + q * 4) = l;
        }
    }
    __syncthreads();

    uint4 rAh, rAl;
    uint2 rBh[4], rBl[4];

    for (int s = 0; s < NSTAGE; s++) {
        if (s + 1 < NSTAGE) {
            int off = (s + 1) * KK;
            rAh = *reinterpret_cast<const uint4*>(gAh + off);
            rAl = *reinterpret_cast<const uint4*>(gAl + off);
            #pragma unroll
            for (int q = 0; q < 4; q++) {
                float4 v = reinterpret_cast<const float4*>(gB + off)[q];
                split4(v, rBh[q], rBl[q]);
            }
        }

        const __nv_bfloat16* st = sm + (s & 1) * STAGE_EL;
        #pragma unroll
        for (int ks = 0; ks < 2; ks++) {
            int kc = ks * 16;
            wmma::load_matrix_sync(aH[0], st + (wb +  0) * LDM + kc, LDM);
            wmma::load_matrix_sync(aH[1], st + (wb + 16) * LDM + kc, LDM);
            wmma::load_matrix_sync(aL[0], st + OFF_AL + (wb +  0) * LDM + kc, LDM);
            wmma::load_matrix_sync(aL[1], st + OFF_AL + (wb + 16) * LDM + kc, LDM);
            wmma::load_matrix_sync(bH[0], st + OFF_BH + (wj +  0) * LDM + kc, LDM);
            wmma::load_matrix_sync(bH[1], st + OFF_BH + (wj + 16) * LDM + kc, LDM);
            wmma::load_matrix_sync(bL[0], st + OFF_BL + (wj +  0) * LDM + kc, LDM);
            wmma::load_matrix_sync(bL[1], st + OFF_BL + (wj + 16) * LDM + kc, LDM);
            #pragma unroll
            for (int i = 0; i < 2; i++)
                #pragma unroll
                for (int j = 0; j < 2; j++) {
                    wmma::mma_sync(c[i][j], aH[i], bH[j], c[i][j]);
                    wmma::mma_sync(c[i][j], aL[i], bH[j], c[i][j]);
                    wmma::mma_sync(c[i][j], aH[i], bL[j], c[i][j]);
                }
        }

        if (s + 1 < NSTAGE) {
            __syncthreads();
            __nv_bfloat16* dt = sm + ((s + 1) & 1) * STAGE_EL;
            *reinterpret_cast<uint4*>(dt + aDst)          = rAh;
            *reinterpret_cast<uint4*>(dt + OFF_AL + aDst) = rAl;
            #pragma unroll
            for (int q = 0; q < 4; q++) {
                *reinterpret_cast<uint2*>(dt + OFF_BH + bDst + q * 4) = rBh[q];
                *reinterpret_cast<uint2*>(dt + OFF_BL + bDst + q * 4) = rBl[q];
            }
            __syncthreads();
        }
    }

    float* dst = g_part + blockIdx.y * (BATCH * D_MODEL);
    #pragma unroll
    for (int i = 0; i < 2; i++)
        #pragma unroll
        for (int j = 0; j < 2; j++)
            wmma::store_matrix_sync(dst + (wb + i * 16) * D_MODEL + j0 + wj + j * 16,
                                    c[i][j], D_MODEL, wmma::mem_row_major);
}

// ---------------------------------------------------------------------------
// Epilogue: reduce KSPLIT=32 partials + SiLU (R3-proven 256x256 config).
// ---------------------------------------------------------------------------
__global__ __launch_bounds__(256) void epilogue(float* __restrict__ out) {
    int i = blockIdx.x * 256 + threadIdx.x;
    float s = 0.0f;
    #pragma unroll
    for (int ks = 0; ks < KSPLIT; ks++)
        s += g_part[ks * (BATCH * D_MODEL) + i];
    out[i] = s / (1.0f + expf(-s));
}

// ---------------------------------------------------------------------------
// Single stream (R14-proven). Inputs: x, t, W, B_p, Pr, Pi, tables (unused).
// ---------------------------------------------------------------------------
extern "C" void kernel_launch(void* const* d_in, const int* in_sizes, int n_in,
                              void* d_out, int out_size) {
    const float* x  = (const float*)d_in[0];
    const float* t  = (const float*)d_in[1];
    const float* W  = (const float*)d_in[2];
    const float* Bp = (const float*)d_in[3];
    const float* Pr = (const float*)d_in[4];
    const float* Pi = (const float*)d_in[5];
    float* out = (float*)d_out;

    static bool init = false;
    if (!init) {
        cudaFuncSetAttribute(gemm_wmma, cudaFuncAttributeMaxDynamicSharedMemorySize, SMEM_B);
        init = true;
    }

    resonant_main<<<NUM_NEURONS / 2, 128>>>(x, t, W, Bp);
    gemm_wmma<<<dim3(D_MODEL / 128, KSPLIT), 256, SMEM_B>>>(Pr, Pi);
    epilogue<<<(BATCH * D_MODEL + 255) / 256, 256>>>(out);
}

// round 16
// speedup vs baseline: 1.2388x; 1.2388x over previous
#include <cuda_runtime.h>
#include <cuda_bf16.h>
#include <mma.h>
#include <math.h>
#include <stdint.h>

using namespace nvcuda;

#define NUM_NEURONS 2048
#define D_MODEL     1024
#define BATCH       64
#define K_TOTAL     4096
#define KSPLIT      32
#define DCHUNK      128
#define XLD         132                       // padded x_sh row stride (floats)

// GEMM tiling (R13/R14-proven)
#define KK        32
#define NSTAGE    ((K_TOTAL / KSPLIT) / KK)   // 4
#define LDM       40
#define OFF_AL    (64 * LDM)
#define OFF_BH    (2 * 64 * LDM)
#define OFF_BL    (OFF_BH + 128 * LDM)
#define STAGE_EL  (OFF_BL + 128 * LDM)
#define SMEM_B    (2 * STAGE_EL * 2)          // 61440 bytes

// Scratch (static device globals — no runtime allocation)
__device__ __align__(256) __nv_bfloat16 g_Ahi[BATCH * K_TOTAL];    // S^T hi [b][k]
__device__ __align__(256) __nv_bfloat16 g_Alo[BATCH * K_TOTAL];    // S^T lo
__device__ __align__(256) float g_part[KSPLIT * BATCH * D_MODEL];  // 8MB

// ---------------------------------------------------------------------------
// FMA-pipe sincos (R3-proven).
// ---------------------------------------------------------------------------
__device__ __forceinline__ void sincos_poly(float th, float& s_out, float& c_out) {
    const float TWO_OVER_PI = 0.636619772f;
    const float MAGIC = 12582912.0f;
    float w   = th * TWO_OVER_PI;
    float big = w + MAGIC;
    int   qi  = __float_as_int(big);
    float r   = big - MAGIC;
    float u   = w - r;
    float u2  = u * u;
    float sp  = fmaf(u2, fmaf(u2, fmaf(u2, -4.6817541e-3f, 7.9692626e-2f),
                              -6.4596410e-1f), 1.57079633f) * u;
    float cp  = fmaf(u2, fmaf(u2, fmaf(u2, -2.0864648e-2f, 2.5369510e-1f),
                              -1.2337006f), 1.0f);
    float ss = (qi & 1) ? cp : sp;
    float cc = (qi & 1) ? sp : cp;
    if (qi & 2)       ss = -ss;
    if ((qi + 1) & 2) cc = -cc;
    s_out = ss; c_out = cc;
}

// ---------------------------------------------------------------------------
// Main: 2 neurons x 64 batches per CTA; 3/4 MUFU + 1/4 FMA-pipe poly;
// rotation identity for +t. x_sh in padded [b][d] layout (conflict-free
// inner LDS.128). FIXED staging (R15 bug): one warp reads ONE x row per
// iteration — 512B contiguous LDG.128 per warp (4 sectors, fully coalesced),
// STS.128 banks 4*lane mod 32 all distinct. 16 independent LDGs/thread.
// Writes bf16 hi/lo S^T directly.
// ---------------------------------------------------------------------------
__global__ __launch_bounds__(128) void resonant_main(const float* __restrict__ x,
                                                     const float* __restrict__ t,
                                                     const float* __restrict__ W,
                                                     const float* __restrict__ Bp) {
    __shared__ __align__(16) float  x_sh[BATCH * XLD];   // 33 KB
    __shared__ __align__(16) float2 rB_sh[2][DCHUNK];    // 2 KB

    int tid  = threadIdx.x;
    int b    = tid & 63;
    int nl   = tid >> 6;
    int n0   = blockIdx.x * 2;
    int wid  = tid >> 5;
    int lane = tid & 31;

    float tb = t[b];
    float cp = 0.0f, sp = 0.0f;

    const float* xrow = &x_sh[b * XLD];

    for (int d0 = 0; d0 < D_MODEL; d0 += DCHUNK) {
        // stage x: warp w handles rows w*16 .. w*16+15, one row per iter,
        // lanes read 32 consecutive float4 (contiguous 512B -> coalesced)
        #pragma unroll
        for (int i = 0; i < 16; i++) {
            int row = wid * 16 + i;
            float4 v = *reinterpret_cast<const float4*>(
                x + row * D_MODEL + d0 + lane * 4);
            *reinterpret_cast<float4*>(&x_sh[row * XLD + lane * 4]) = v;
        }
        {
            float w0 = W [(n0 + 0) * D_MODEL + d0 + tid];
            float p0 = Bp[(n0 + 0) * D_MODEL + d0 + tid];
            rB_sh[0][tid] = make_float2(__fdividef(1.0f, 1.0f + fabsf(w0)), p0);
            float w1 = W [(n0 + 1) * D_MODEL + d0 + tid];
            float p1 = Bp[(n0 + 1) * D_MODEL + d0 + tid];
            rB_sh[1][tid] = make_float2(__fdividef(1.0f, 1.0f + fabsf(w1)), p1);
        }
        __syncthreads();

        #pragma unroll
        for (int dd = 0; dd < DCHUNK; dd += 4) {
            float4 xv  = *reinterpret_cast<const float4*>(xrow + dd);
            float4 r01 = *reinterpret_cast<const float4*>(&rB_sh[nl][dd]);     // {r0,B0,r1,B1}
            float4 r23 = *reinterpret_cast<const float4*>(&rB_sh[nl][dd + 2]); // {r2,B2,r3,B3}
            float s, c;
            {
                float th = fmaf(xv.x, r01.x, r01.y);
                __sincosf(th, &s, &c); cp += c; sp += s;
            }
            {
                float th = fmaf(xv.y, r01.z, r01.w);
                __sincosf(th, &s, &c); cp += c; sp += s;
            }
            {
                float th = fmaf(xv.z, r23.x, r23.y);
                __sincosf(th, &s, &c); cp += c; sp += s;
            }
            {
                float th = fmaf(xv.w, r23.z, r23.w);
                sincos_poly(th, s, c); cp += c; sp += s;
            }
        }
        __syncthreads();
    }

    // rotate by t_b (exact identity)
    float st_, ct_;
    __sincosf(tb, &st_, &ct_);
    float cs = ct_ * cp - st_ * sp;
    float sn = st_ * cp + ct_ * sp;

    int n = n0 + nl;
    __nv_bfloat16 ch = __float2bfloat16(cs);
    g_Ahi[b * K_TOTAL + n] = ch;
    g_Alo[b * K_TOTAL + n] = __float2bfloat16(cs - __bfloat162float(ch));
    __nv_bfloat16 sh = __float2bfloat16(sn);
    g_Ahi[b * K_TOTAL + n + NUM_NEURONS] = sh;
    g_Alo[b * K_TOTAL + n + NUM_NEURONS] = __float2bfloat16(sn - __bfloat162float(sh));
}

// ---------------------------------------------------------------------------
// bf16 hi/lo split of a float4 into two packed uint2.
// ---------------------------------------------------------------------------
__device__ __forceinline__ void split4(float4 v, uint2& hi, uint2& lo) {
    __nv_bfloat162 h0 = __floats2bfloat162_rn(v.x, v.y);
    __nv_bfloat162 h1 = __floats2bfloat162_rn(v.z, v.w);
    float2 f0 = __bfloat1622float2(h0);
    float2 f1 = __bfloat1622float2(h1);
    __nv_bfloat162 l0 = __floats2bfloat162_rn(v.x - f0.x, v.y - f0.y);
    __nv_bfloat162 l1 = __floats2bfloat162_rn(v.z - f1.x, v.w - f1.y);
    hi.x = *reinterpret_cast<uint32_t*>(&h0);
    hi.y = *reinterpret_cast<uint32_t*>(&h1);
    lo.x = *reinterpret_cast<uint32_t*>(&l0);
    lo.y = *reinterpret_cast<uint32_t*>(&l1);
}

// ---------------------------------------------------------------------------
// Tensor-core GEMM (R14-proven, untouched): smem-staged wmma, double buffer,
// reg prefetch, inline fp32->bf16 hi/lo conversion of P during staging.
// CTA = 64b x 128j, 8 warps, 4 stages of KK=32; grid (8,32)=256 CTAs.
// ---------------------------------------------------------------------------
__global__ __launch_bounds__(256) void gemm_wmma(const float* __restrict__ Pr,
                                                 const float* __restrict__ Pi) {
    extern __shared__ __nv_bfloat16 sm[];

    int tid  = threadIdx.x;
    int warp = tid >> 5;
    int wb   = (warp >> 2) * 32;
    int wj   = (warp & 3) * 32;
    int j0   = blockIdx.x * 128;
    int k0   = blockIdx.y * (K_TOTAL / KSPLIT);

    const float* P     = (k0 < NUM_NEURONS) ? Pr : Pi;
    int          kbase = (k0 < NUM_NEURONS) ? k0 : k0 - NUM_NEURONS;

    int arow = tid >> 2, achk = (tid & 3) * 8;
    const __nv_bfloat16* gAh = g_Ahi + arow * K_TOTAL + k0 + achk;
    const __nv_bfloat16* gAl = g_Alo + arow * K_TOTAL + k0 + achk;
    int brow0 = tid >> 1, bchk0 = (tid & 1) * 16;
    const float* gB = P + (j0 + brow0) * NUM_NEURONS + kbase + bchk0;

    uint32_t aDst = arow * LDM + achk;
    uint32_t bDst = brow0 * LDM + bchk0;

    wmma::fragment<wmma::matrix_a, 16, 16, 16, __nv_bfloat16, wmma::row_major> aH[2], aL[2];
    wmma::fragment<wmma::matrix_b, 16, 16, 16, __nv_bfloat16, wmma::col_major> bH[2], bL[2];
    wmma::fragment<wmma::accumulator, 16, 16, 16, float> c[2][2];
    #pragma unroll
    for (int i = 0; i < 2; i++)
        #pragma unroll
        for (int j = 0; j < 2; j++) wmma::fill_fragment(c[i][j], 0.0f);

    {   // stage 0
        __nv_bfloat16* st = sm;
        *reinterpret_cast<uint4*>(st + aDst)          = *reinterpret_cast<const uint4*>(gAh);
        *reinterpret_cast<uint4*>(st + OFF_AL + aDst) = *reinterpret_cast<const uint4*>(gAl);
        #pragma unroll
        for (int q = 0; q < 4; q++) {
            float4 v = reinterpret_cast<const float4*>(gB)[q];
            uint2 h, l;
            split4(v, h, l);
            *reinterpret_cast<uint2*>(st + OFF_BH + bDst + q * 4) = h;
            *reinterpret_cast<uint2*>(st + OFF_BL + bDst + q * 4) = l;
        }
    }
    __syncthreads();

    uint4 rAh, rAl;
    uint2 rBh[4], rBl[4];

    for (int s = 0; s < NSTAGE; s++) {
        if (s + 1 < NSTAGE) {
            int off = (s + 1) * KK;
            rAh = *reinterpret_cast<const uint4*>(gAh + off);
            rAl = *reinterpret_cast<const uint4*>(gAl + off);
            #pragma unroll
            for (int q = 0; q < 4; q++) {
                float4 v = reinterpret_cast<const float4*>(gB + off)[q];
                split4(v, rBh[q], rBl[q]);
            }
        }

        const __nv_bfloat16* st = sm + (s & 1) * STAGE_EL;
        #pragma unroll
        for (int ks = 0; ks < 2; ks++) {
            int kc = ks * 16;
            wmma::load_matrix_sync(aH[0], st + (wb +  0) * LDM + kc, LDM);
            wmma::load_matrix_sync(aH[1], st + (wb + 16) * LDM + kc, LDM);
            wmma::load_matrix_sync(aL[0], st + OFF_AL + (wb +  0) * LDM + kc, LDM);
            wmma::load_matrix_sync(aL[1], st + OFF_AL + (wb + 16) * LDM + kc, LDM);
            wmma::load_matrix_sync(bH[0], st + OFF_BH + (wj +  0) * LDM + kc, LDM);
            wmma::load_matrix_sync(bH[1], st + OFF_BH + (wj + 16) * LDM + kc, LDM);
            wmma::load_matrix_sync(bL[0], st + OFF_BL + (wj +  0) * LDM + kc, LDM);
            wmma::load_matrix_sync(bL[1], st + OFF_BL + (wj + 16) * LDM + kc, LDM);
            #pragma unroll
            for (int i = 0; i < 2; i++)
                #pragma unroll
                for (int j = 0; j < 2; j++) {
                    wmma::mma_sync(c[i][j], aH[i], bH[j], c[i][j]);
                    wmma::mma_sync(c[i][j], aL[i], bH[j], c[i][j]);
                    wmma::mma_sync(c[i][j], aH[i], bL[j], c[i][j]);
                }
        }

        if (s + 1 < NSTAGE) {
            __syncthreads();
            __nv_bfloat16* dt = sm + ((s + 1) & 1) * STAGE_EL;
            *reinterpret_cast<uint4*>(dt + aDst)          = rAh;
            *reinterpret_cast<uint4*>(dt + OFF_AL + aDst) = rAl;
            #pragma unroll
            for (int q = 0; q < 4; q++) {
                *reinterpret_cast<uint2*>(dt + OFF_BH + bDst + q * 4) = rBh[q];
                *reinterpret_cast<uint2*>(dt + OFF_BL + bDst + q * 4) = rBl[q];
            }
            __syncthreads();
        }
    }

    float* dst = g_part + blockIdx.y * (BATCH * D_MODEL);
    #pragma unroll
    for (int i = 0; i < 2; i++)
        #pragma unroll
        for (int j = 0; j < 2; j++)
            wmma::store_matrix_sync(dst + (wb + i * 16) * D_MODEL + j0 + wj + j * 16,
                                    c[i][j], D_MODEL, wmma::mem_row_major);
}

// ---------------------------------------------------------------------------
// Epilogue: reduce KSPLIT=32 partials + SiLU (R3-proven 256x256 config).
// ---------------------------------------------------------------------------
__global__ __launch_bounds__(256) void epilogue(float* __restrict__ out) {
    int i = blockIdx.x * 256 + threadIdx.x;
    float s = 0.0f;
    #pragma unroll
    for (int ks = 0; ks < KSPLIT; ks++)
        s += g_part[ks * (BATCH * D_MODEL) + i];
    out[i] = s / (1.0f + expf(-s));
}

// ---------------------------------------------------------------------------
// Single stream (R14-proven). Inputs: x, t, W, B_p, Pr, Pi, tables (unused).
// ---------------------------------------------------------------------------
extern "C" void kernel_launch(void* const* d_in, const int* in_sizes, int n_in,
                              void* d_out, int out_size) {
    const float* x  = (const float*)d_in[0];
    const float* t  = (const float*)d_in[1];
    const float* W  = (const float*)d_in[2];
    const float* Bp = (const float*)d_in[3];
    const float* Pr = (const float*)d_in[4];
    const float* Pi = (const float*)d_in[5];
    float* out = (float*)d_out;

    static bool init = false;
    if (!init) {
        cudaFuncSetAttribute(gemm_wmma, cudaFuncAttributeMaxDynamicSharedMemorySize, SMEM_B);
        init = true;
    }

    resonant_main<<<NUM_NEURONS / 2, 128>>>(x, t, W, Bp);
    gemm_wmma<<<dim3(D_MODEL / 128, KSPLIT), 256, SMEM_B>>>(Pr, Pi);
    epilogue<<<(BATCH * D_MODEL + 255) / 256, 256>>>(out);
}

// round 17
// speedup vs baseline: 1.2690x; 1.0244x over previous
#include <cuda_runtime.h>
#include <cuda_bf16.h>
#include <mma.h>
#include <math.h>
#include <stdint.h>

using namespace nvcuda;

#define NUM_NEURONS 2048
#define D_MODEL     1024
#define BATCH       64
#define K_TOTAL     4096
#define KSPLIT      32
#define DCHUNK      64
#define XLD         68                        // padded x_sh row stride (floats)

// GEMM tiling (R13/R14-proven)
#define KK        32
#define NSTAGE    ((K_TOTAL / KSPLIT) / KK)   // 4
#define LDM       40
#define OFF_AL    (64 * LDM)
#define OFF_BH    (2 * 64 * LDM)
#define OFF_BL    (OFF_BH + 128 * LDM)
#define STAGE_EL  (OFF_BL + 128 * LDM)
#define SMEM_B    (2 * STAGE_EL * 2)          // 61440 bytes

// Scratch (static device globals — no runtime allocation)
__device__ __align__(256) __nv_bfloat16 g_Ahi[BATCH * K_TOTAL];    // S^T hi [b][k]
__device__ __align__(256) __nv_bfloat16 g_Alo[BATCH * K_TOTAL];    // S^T lo
__device__ __align__(256) float g_part[KSPLIT * BATCH * D_MODEL];  // 8MB

// ---------------------------------------------------------------------------
// FMA-pipe sincos (R3-proven).
// ---------------------------------------------------------------------------
__device__ __forceinline__ void sincos_poly(float th, float& s_out, float& c_out) {
    const float TWO_OVER_PI = 0.636619772f;
    const float MAGIC = 12582912.0f;
    float w   = th * TWO_OVER_PI;
    float big = w + MAGIC;
    int   qi  = __float_as_int(big);
    float r   = big - MAGIC;
    float u   = w - r;
    float u2  = u * u;
    float sp  = fmaf(u2, fmaf(u2, fmaf(u2, -4.6817541e-3f, 7.9692626e-2f),
                              -6.4596410e-1f), 1.57079633f) * u;
    float cp  = fmaf(u2, fmaf(u2, fmaf(u2, -2.0864648e-2f, 2.5369510e-1f),
                              -1.2337006f), 1.0f);
    float ss = (qi & 1) ? cp : sp;
    float cc = (qi & 1) ? sp : cp;
    if (qi & 2)       ss = -ss;
    if ((qi + 1) & 2) cc = -cc;
    s_out = ss; c_out = cc;
}

// ---------------------------------------------------------------------------
// Main: 2 neurons x 64 batches per CTA; 3/4 MUFU + 1/4 FMA-pipe poly;
// rotation identity for +t; coalesced warp-row staging (R16-proven).
// NEW (occupancy): DCHUNK=64 -> x_sh 17.4KB (was 33.8) and launch_bounds
// (128,7) caps regs at 73 -> 7 CTAs/SM (was 6, occ 28.5%, issue 59%).
// XLD=68 preserves conflict-free LDS.128 / STS.128 (banks (4b+dd) mod 32).
// ---------------------------------------------------------------------------
__global__ __launch_bounds__(128, 7) void resonant_main(const float* __restrict__ x,
                                                        const float* __restrict__ t,
                                                        const float* __restrict__ W,
                                                        const float* __restrict__ Bp) {
    __shared__ __align__(16) float  x_sh[BATCH * XLD];   // 17.4 KB
    __shared__ __align__(16) float2 rB_sh[2][DCHUNK];    // 1 KB

    int tid  = threadIdx.x;
    int b    = tid & 63;
    int nl   = tid >> 6;
    int n0   = blockIdx.x * 2;
    int wid  = tid >> 5;
    int lane = tid & 31;

    float tb = t[b];
    float cp = 0.0f, sp = 0.0f;

    const float* xrow = &x_sh[b * XLD];

    // rB staging: one load per thread (tid>>6 = neuron, tid&63 = col)
    int rcol = tid & 63;

    for (int d0 = 0; d0 < D_MODEL; d0 += DCHUNK) {
        // stage x: warp handles rows wid*16..+15, two rows per iter;
        // half-warp reads 256B contiguous (coalesced); STS conflict-free.
        #pragma unroll
        for (int i = 0; i < 16; i += 2) {
            int row = wid * 16 + i + (lane >> 4);
            int col = (lane & 15) * 4;
            float4 v = *reinterpret_cast<const float4*>(x + row * D_MODEL + d0 + col);
            *reinterpret_cast<float4*>(&x_sh[row * XLD + col]) = v;
        }
        {
            float w = W [(n0 + nl) * D_MODEL + d0 + rcol];
            float p = Bp[(n0 + nl) * D_MODEL + d0 + rcol];
            rB_sh[nl][rcol] = make_float2(__fdividef(1.0f, 1.0f + fabsf(w)), p);
        }
        __syncthreads();

        #pragma unroll
        for (int dd = 0; dd < DCHUNK; dd += 4) {
            float4 xv  = *reinterpret_cast<const float4*>(xrow + dd);
            float4 r01 = *reinterpret_cast<const float4*>(&rB_sh[nl][dd]);     // {r0,B0,r1,B1}
            float4 r23 = *reinterpret_cast<const float4*>(&rB_sh[nl][dd + 2]); // {r2,B2,r3,B3}
            float s, c;
            {
                float th = fmaf(xv.x, r01.x, r01.y);
                __sincosf(th, &s, &c); cp += c; sp += s;
            }
            {
                float th = fmaf(xv.y, r01.z, r01.w);
                __sincosf(th, &s, &c); cp += c; sp += s;
            }
            {
                float th = fmaf(xv.z, r23.x, r23.y);
                __sincosf(th, &s, &c); cp += c; sp += s;
            }
            {
                float th = fmaf(xv.w, r23.z, r23.w);
                sincos_poly(th, s, c); cp += c; sp += s;
            }
        }
        __syncthreads();
    }

    // rotate by t_b (exact identity)
    float st_, ct_;
    __sincosf(tb, &st_, &ct_);
    float cs = ct_ * cp - st_ * sp;
    float sn = st_ * cp + ct_ * sp;

    int n = n0 + nl;
    __nv_bfloat16 ch = __float2bfloat16(cs);
    g_Ahi[b * K_TOTAL + n] = ch;
    g_Alo[b * K_TOTAL + n] = __float2bfloat16(cs - __bfloat162float(ch));
    __nv_bfloat16 sh = __float2bfloat16(sn);
    g_Ahi[b * K_TOTAL + n + NUM_NEURONS] = sh;
    g_Alo[b * K_TOTAL + n + NUM_NEURONS] = __float2bfloat16(sn - __bfloat162float(sh));
}

// ---------------------------------------------------------------------------
// bf16 hi/lo split of a float4 into two packed uint2.
// ---------------------------------------------------------------------------
__device__ __forceinline__ void split4(float4 v, uint2& hi, uint2& lo) {
    __nv_bfloat162 h0 = __floats2bfloat162_rn(v.x, v.y);
    __nv_bfloat162 h1 = __floats2bfloat162_rn(v.z, v.w);
    float2 f0 = __bfloat1622float2(h0);
    float2 f1 = __bfloat1622float2(h1);
    __nv_bfloat162 l0 = __floats2bfloat162_rn(v.x - f0.x, v.y - f0.y);
    __nv_bfloat162 l1 = __floats2bfloat162_rn(v.z - f1.x, v.w - f1.y);
    hi.x = *reinterpret_cast<uint32_t*>(&h0);
    hi.y = *reinterpret_cast<uint32_t*>(&h1);
    lo.x = *reinterpret_cast<uint32_t*>(&l0);
    lo.y = *reinterpret_cast<uint32_t*>(&l1);
}

// ---------------------------------------------------------------------------
// Tensor-core GEMM (R14/R16-proven, untouched): smem-staged wmma, double
// buffer, reg prefetch, inline fp32->bf16 hi/lo conversion of P.
// CTA = 64b x 128j, 8 warps, 4 stages of KK=32; grid (8,32)=256 CTAs.
// ---------------------------------------------------------------------------
__global__ __launch_bounds__(256) void gemm_wmma(const float* __restrict__ Pr,
                                                 const float* __restrict__ Pi) {
    extern __shared__ __nv_bfloat16 sm[];

    int tid  = threadIdx.x;
    int warp = tid >> 5;
    int wb   = (warp >> 2) * 32;
    int wj   = (warp & 3) * 32;
    int j0   = blockIdx.x * 128;
    int k0   = blockIdx.y * (K_TOTAL / KSPLIT);

    const float* P     = (k0 < NUM_NEURONS) ? Pr : Pi;
    int          kbase = (k0 < NUM_NEURONS) ? k0 : k0 - NUM_NEURONS;

    int arow = tid >> 2, achk = (tid & 3) * 8;
    const __nv_bfloat16* gAh = g_Ahi + arow * K_TOTAL + k0 + achk;
    const __nv_bfloat16* gAl = g_Alo + arow * K_TOTAL + k0 + achk;
    int brow0 = tid >> 1, bchk0 = (tid & 1) * 16;
    const float* gB = P + (j0 + brow0) * NUM_NEURONS + kbase + bchk0;

    uint32_t aDst = arow * LDM + achk;
    uint32_t bDst = brow0 * LDM + bchk0;

    wmma::fragment<wmma::matrix_a, 16, 16, 16, __nv_bfloat16, wmma::row_major> aH[2], aL[2];
    wmma::fragment<wmma::matrix_b, 16, 16, 16, __nv_bfloat16, wmma::col_major> bH[2], bL[2];
    wmma::fragment<wmma::accumulator, 16, 16, 16, float> c[2][2];
    #pragma unroll
    for (int i = 0; i < 2; i++)
        #pragma unroll
        for (int j = 0; j < 2; j++) wmma::fill_fragment(c[i][j], 0.0f);

    {   // stage 0
        __nv_bfloat16* st = sm;
        *reinterpret_cast<uint4*>(st + aDst)          = *reinterpret_cast<const uint4*>(gAh);
        *reinterpret_cast<uint4*>(st + OFF_AL + aDst) = *reinterpret_cast<const uint4*>(gAl);
        #pragma unroll
        for (int q = 0; q < 4; q++) {
            float4 v = reinterpret_cast<const float4*>(gB)[q];
            uint2 h, l;
            split4(v, h, l);
            *reinterpret_cast<uint2*>(st + OFF_BH + bDst + q * 4) = h;
            *reinterpret_cast<uint2*>(st + OFF_BL + bDst + q * 4) = l;
        }
    }
    __syncthreads();

    uint4 rAh, rAl;
    uint2 rBh[4], rBl[4];

    for (int s = 0; s < NSTAGE; s++) {
        if (s + 1 < NSTAGE) {
            int off = (s + 1) * KK;
            rAh = *reinterpret_cast<const uint4*>(gAh + off);
            rAl = *reinterpret_cast<const uint4*>(gAl + off);
            #pragma unroll
            for (int q = 0; q < 4; q++) {
                float4 v = reinterpret_cast<const float4*>(gB + off)[q];
                split4(v, rBh[q], rBl[q]);
            }
        }

        const __nv_bfloat16* st = sm + (s & 1) * STAGE_EL;
        #pragma unroll
        for (int ks = 0; ks < 2; ks++) {
            int kc = ks * 16;
            wmma::load_matrix_sync(aH[0], st + (wb +  0) * LDM + kc, LDM);
            wmma::load_matrix_sync(aH[1], st + (wb + 16) * LDM + kc, LDM);
            wmma::load_matrix_sync(aL[0], st + OFF_AL + (wb +  0) * LDM + kc, LDM);
            wmma::load_matrix_sync(aL[1], st + OFF_AL + (wb + 16) * LDM + kc, LDM);
            wmma::load_matrix_sync(bH[0], st + OFF_BH + (wj +  0) * LDM + kc, LDM);
            wmma::load_matrix_sync(bH[1], st + OFF_BH + (wj + 16) * LDM + kc, LDM);
            wmma::load_matrix_sync(bL[0], st + OFF_BL + (wj +  0) * LDM + kc, LDM);
            wmma::load_matrix_sync(bL[1], st + OFF_BL + (wj + 16) * LDM + kc, LDM);
            #pragma unroll
            for (int i = 0; i < 2; i++)
                #pragma unroll
                for (int j = 0; j < 2; j++) {
                    wmma::mma_sync(c[i][j], aH[i], bH[j], c[i][j]);
                    wmma::mma_sync(c[i][j], aL[i], bH[j], c[i][j]);
                    wmma::mma_sync(c[i][j], aH[i], bL[j], c[i][j]);
                }
        }

        if (s + 1 < NSTAGE) {
            __syncthreads();
            __nv_bfloat16* dt = sm + ((s + 1) & 1) * STAGE_EL;
            *reinterpret_cast<uint4*>(dt + aDst)          = rAh;
            *reinterpret_cast<uint4*>(dt + OFF_AL + aDst) = rAl;
            #pragma unroll
            for (int q = 0; q < 4; q++) {
                *reinterpret_cast<uint2*>(dt + OFF_BH + bDst + q * 4) = rBh[q];
                *reinterpret_cast<uint2*>(dt + OFF_BL + bDst + q * 4) = rBl[q];
            }
            __syncthreads();
        }
    }

    float* dst = g_part + blockIdx.y * (BATCH * D_MODEL);
    #pragma unroll
    for (int i = 0; i < 2; i++)
        #pragma unroll
        for (int j = 0; j < 2; j++)
            wmma::store_matrix_sync(dst + (wb + i * 16) * D_MODEL + j0 + wj + j * 16,
                                    c[i][j], D_MODEL, wmma::mem_row_major);
}

// ---------------------------------------------------------------------------
// Epilogue: reduce KSPLIT=32 partials + SiLU (R3-proven 256x256 config).
// ---------------------------------------------------------------------------
__global__ __launch_bounds__(256) void epilogue(float* __restrict__ out) {
    int i = blockIdx.x * 256 + threadIdx.x;
    float s = 0.0f;
    #pragma unroll
    for (int ks = 0; ks < KSPLIT; ks++)
        s += g_part[ks * (BATCH * D_MODEL) + i];
    out[i] = s / (1.0f + expf(-s));
}

// ---------------------------------------------------------------------------
// Single stream (R14-proven). Inputs: x, t, W, B_p, Pr, Pi, tables (unused).
// ---------------------------------------------------------------------------
extern "C" void kernel_launch(void* const* d_in, const int* in_sizes, int n_in,
                              void* d_out, int out_size) {
    const float* x  = (const float*)d_in[0];
    const float* t  = (const float*)d_in[1];
    const float* W  = (const float*)d_in[2];
    const float* Bp = (const float*)d_in[3];
    const float* Pr = (const float*)d_in[4];
    const float* Pi = (const float*)d_in[5];
    float* out = (float*)d_out;

    static bool init = false;
    if (!init) {
        cudaFuncSetAttribute(gemm_wmma, cudaFuncAttributeMaxDynamicSharedMemorySize, SMEM_B);
        init = true;
    }

    resonant_main<<<NUM_NEURONS / 2, 128>>>(x, t, W, Bp);
    gemm_wmma<<<dim3(D_MODEL / 128, KSPLIT), 256, SMEM_B>>>(Pr, Pi);
    epilogue<<<(BATCH * D_MODEL + 255) / 256, 256>>>(out);
}